// round 4
// baseline (speedup 1.0000x reference)
#include <cuda_runtime.h>
#include <cuda_bf16.h>
#include <math.h>

#define BG   128
#define NPG  256
#define EPG  2048
#define EMB  256
#define NL   5
#define NTOT (BG*NPG)     // 32768 nodes
#define ETOT (BG*EPG)     // 262144 edges

typedef unsigned long long ull;

// ------------------------------ scratch (device globals; no allocs) ---------
__device__ ull   g_pack[(size_t)BG*NPG*NPG];
__device__ float g_A   [(size_t)BG*NPG*NPG];
__device__ float g_h  [NTOT*EMB];
__device__ float g_x1 [NTOT*EMB];
__device__ float g_x2 [NTOT*EMB];
__device__ float g_hin[NTOT*EMB];
__device__ float g_z  [NTOT*EMB];
__device__ float g_t  [NTOT*2*EMB];
__device__ float g_h2 [NTOT*EMB];
__device__ float g_vn [BG*EMB];
__device__ float g_vt [BG*EMB];
__device__ float g_vh [BG*2*EMB];
__device__ float g_ewt[16];
__device__ int   g_deg[NTOT];
__device__ int   g_ptr[NTOT];
__device__ int   g_cur[NTOT];
__device__ int   g_csrc[ETOT];
__device__ int   g_cea [ETOT];
__device__ float g_sum[2*EMB];
__device__ float g_sq [2*EMB];
__device__ float g_sc1[2*EMB];
__device__ float g_sh1[2*EMB];
__device__ float g_sc2[EMB];
__device__ float g_sh2[EMB];

// ------------------------------ setup kernels -------------------------------
__global__ void k_zero() {
    size_t i = (size_t)blockIdx.x * 256 + threadIdx.x;
    if (i < (size_t)BG*NPG*NPG) g_pack[i] = 0ull;
    if (i < NTOT) g_deg[i] = 0;
}

__global__ void k_ewt(const float* __restrict__ bh, const float* __restrict__ w,
                      const float* __restrict__ b) {
    int warp = threadIdx.x >> 5, lane = threadIdx.x & 31;
    if (warp < 16) {
        float v = bh[warp*64 + lane] * w[lane] + bh[warp*64 + 32 + lane] * w[32 + lane];
        #pragma unroll
        for (int o = 16; o; o >>= 1) v += __shfl_down_sync(0xffffffffu, v, o);
        if (lane == 0) g_ewt[warp] = 1.f / (1.f + expf(-(v + b[0])));
    }
}

__global__ void k_scatter(const int* __restrict__ lei, const int* __restrict__ eai) {
    int idx = blockIdx.x * 256 + threadIdx.x;
    if (idx >= ETOT) return;
    int b = idx / EPG, k = idx - b * EPG;
    int s = lei[(size_t)b*2*EPG + k];
    int d = lei[(size_t)b*2*EPG + EPG + k];
    int t = eai[idx];
    float w = g_ewt[t];
    ull key = ((ull)(k + 1) << 32) | (ull)__float_as_uint(w);
    atomicMax(&g_pack[(size_t)b*NPG*NPG + (size_t)s*NPG + d], key);
    atomicAdd(&g_deg[b*NPG + d], 1);
}

__global__ void k_adjfin() {
    int g = blockIdx.x, tid = threadIdx.x;
    __shared__ float cs[NPG], rs[NPG];
    const ull* P = g_pack + (size_t)g*NPG*NPG;
    float*     A = g_A    + (size_t)g*NPG*NPG;
    float c = 0.f;
    for (int i = 0; i < NPG; i++) {
        ull p = P[(size_t)i*NPG + tid];
        float v = p ? __uint_as_float((unsigned)(p & 0xffffffffu)) : 0.f;
        if (i == tid) v += 1.f;
        A[(size_t)i*NPG + tid] = v;
        c += v;
    }
    cs[tid] = rsqrtf(c);
    __syncthreads();
    float r = 0.f;
    for (int j = 0; j < NPG; j++) r += A[(size_t)tid*NPG + j];
    rs[tid] = rsqrtf(r);
    __syncthreads();
    for (int i = 0; i < NPG; i++)
        A[(size_t)i*NPG + tid] *= cs[i] * rs[tid];
}

__global__ void k_scan() {
    int g = blockIdx.x, tid = threadIdx.x;
    __shared__ int s[NPG];
    int d = g_deg[g*NPG + tid];
    s[tid] = d;
    __syncthreads();
    for (int off = 1; off < NPG; off <<= 1) {
        int v = (tid >= off) ? s[tid - off] : 0;
        __syncthreads();
        s[tid] += v;
        __syncthreads();
    }
    int excl = s[tid] - d;
    g_ptr[g*NPG + tid] = g*EPG + excl;
    g_cur[g*NPG + tid] = g*EPG + excl;
}

__global__ void k_csrfill(const int* __restrict__ lei, const int* __restrict__ eai) {
    int idx = blockIdx.x * 256 + threadIdx.x;
    if (idx >= ETOT) return;
    int b = idx / EPG, k = idx - b * EPG;
    int s = lei[(size_t)b*2*EPG + k];
    int d = lei[(size_t)b*2*EPG + EPG + k];
    int pos = atomicAdd(&g_cur[b*NPG + d], 1);
    g_csrc[pos] = b*NPG + s;
    g_cea [pos] = eai[idx];
}

// h0 = atom_emb[atom_idx]; g_h pre-scaled by 0.25 (the /(order+1))
__global__ void k_gather(const int* __restrict__ aidx, const float* __restrict__ aemb) {
    int idx = blockIdx.x * 256 + threadIdx.x;
    int n = idx >> 8, c = idx & 255;
    float v = aemb[aidx[n]*EMB + c];
    g_h[idx]  = 0.25f * v;
    g_x1[idx] = v;
}

// ------------------------------ bf16x3 tensor-core GEMM (2-stage pipeline) --
// fp32-accurate: x = hi + lo (bf16), A@B ~= Ah@Bh + Ah@Bl + Al@Bh
// CTA tile 128x64x16, 8 warps (4x2), warp tile 32x32, mma.m16n8k16.bf16
#define BM 128
#define BN 64
#define BK 16
#define AST 12     // word stride, conflict-free a-frag LDS
#define BST 72     // word stride (72%32==8), conflict-free b-frag LDS

__device__ __forceinline__ unsigned pack2(float e, float o) {
    unsigned r;
    asm("cvt.rn.bf16x2.f32 %0, %1, %2;" : "=r"(r) : "f"(o), "f"(e));
    return r;
}
__device__ __forceinline__ void split2(float e, float o, unsigned &hi, unsigned &lo) {
    float he = __bfloat162float(__float2bfloat16(e));
    float ho = __bfloat162float(__float2bfloat16(o));
    hi = pack2(e, o);
    lo = pack2(e - he, o - ho);
}

#define MMA_BF16(c, a, b)                                                     \
    asm volatile(                                                             \
        "mma.sync.aligned.m16n8k16.row.col.f32.bf16.bf16.f32 "                \
        "{%0,%1,%2,%3}, {%4,%5,%6,%7}, {%8,%9}, {%0,%1,%2,%3};\n"             \
        : "+f"((c)[0]), "+f"((c)[1]), "+f"((c)[2]), "+f"((c)[3])              \
        : "r"((a)[0]), "r"((a)[1]), "r"((a)[2]), "r"((a)[3]),                 \
          "r"((b)[0]), "r"((b)[1]))

// mode: 0 = C=acc+bias, 1 = C=relu(acc+bias), 2 = C=acc, Y += 0.25*acc
// asc/ash: optional per-K-column transform of A: a = relu(a*asc[k]+ash[k])
// ssum/ssq: optional per-column stats of C (post-bias), atomically accumulated
__global__ void __launch_bounds__(256)
k_mma(const float* __restrict__ A, const float* __restrict__ B,
      const float* __restrict__ bias, float* __restrict__ C, float* __restrict__ Y,
      int M, int N, int K, int mode,
      long strideA, long strideB, long strideC,
      const float* __restrict__ asc, const float* __restrict__ ash,
      float* __restrict__ ssum, float* __restrict__ ssq) {
    A += (size_t)blockIdx.z * strideA;
    B += (size_t)blockIdx.z * strideB;
    C += (size_t)blockIdx.z * strideC;
    if (Y) Y += (size_t)blockIdx.z * strideC;

    __shared__ unsigned Ah[2][BM][AST], Al[2][BM][AST];
    __shared__ unsigned Bh[2][8][BST],  Bl[2][8][BST];
    __shared__ float s1[BN], s2[BN];

    int tid  = threadIdx.x;
    int lane = tid & 31, warp = tid >> 5;
    int wm = warp >> 1, wn = warp & 1;
    int bm = blockIdx.y * BM, bn = blockIdx.x * BN;

    int a_r0 = tid >> 2;
    int a_c  = (tid & 3) << 2;
    int a_k2 = (tid & 3) << 1;
    int b_k2 = tid >> 5;
    int b_n  = lane << 1;

    int gid = lane >> 2, tig = lane & 3;

    float4 ra0, ra1; float2 rbe, rbo;

#define LDG_TILE(K0)                                                              \
    {   int kk = (K0);                                                            \
        ra0 = *reinterpret_cast<const float4*>(A + (size_t)(bm + a_r0     )*K + kk + a_c); \
        ra1 = *reinterpret_cast<const float4*>(A + (size_t)(bm + a_r0 + 64)*K + kk + a_c); \
        const float* Bp = B + (size_t)(kk + 2*b_k2)*N + bn + b_n;                 \
        rbe = *reinterpret_cast<const float2*>(Bp);                               \
        rbo = *reinterpret_cast<const float2*>(Bp + N);                           \
        if (asc) {                                                                \
            float4 sc = *reinterpret_cast<const float4*>(asc + kk + a_c);         \
            float4 sh = *reinterpret_cast<const float4*>(ash + kk + a_c);         \
            ra0.x = fmaxf(ra0.x*sc.x+sh.x, 0.f); ra0.y = fmaxf(ra0.y*sc.y+sh.y, 0.f); \
            ra0.z = fmaxf(ra0.z*sc.z+sh.z, 0.f); ra0.w = fmaxf(ra0.w*sc.w+sh.w, 0.f); \
            ra1.x = fmaxf(ra1.x*sc.x+sh.x, 0.f); ra1.y = fmaxf(ra1.y*sc.y+sh.y, 0.f); \
            ra1.z = fmaxf(ra1.z*sc.z+sh.z, 0.f); ra1.w = fmaxf(ra1.w*sc.w+sh.w, 0.f); \
        }                                                                         \
    }

#define STS_TILE(BUF)                                                             \
    {   unsigned hi0, lo0, hi1, lo1;                                              \
        split2(ra0.x, ra0.y, hi0, lo0); split2(ra0.z, ra0.w, hi1, lo1);           \
        Ah[BUF][a_r0][a_k2] = hi0;   Al[BUF][a_r0][a_k2]   = lo0;                 \
        Ah[BUF][a_r0][a_k2+1] = hi1; Al[BUF][a_r0][a_k2+1] = lo1;                 \
        split2(ra1.x, ra1.y, hi0, lo0); split2(ra1.z, ra1.w, hi1, lo1);           \
        Ah[BUF][a_r0+64][a_k2] = hi0;   Al[BUF][a_r0+64][a_k2]   = lo0;           \
        Ah[BUF][a_r0+64][a_k2+1] = hi1; Al[BUF][a_r0+64][a_k2+1] = lo1;           \
        split2(rbe.x, rbo.x, hi0, lo0); split2(rbe.y, rbo.y, hi1, lo1);           \
        Bh[BUF][b_k2][b_n] = hi0;   Bl[BUF][b_k2][b_n]   = lo0;                   \
        Bh[BUF][b_k2][b_n+1] = hi1; Bl[BUF][b_k2][b_n+1] = lo1;                   \
    }

    float acc[2][4][4];
    #pragma unroll
    for (int i = 0; i < 2; i++)
        #pragma unroll
        for (int j = 0; j < 4; j++)
            #pragma unroll
            for (int r = 0; r < 4; r++) acc[i][j][r] = 0.f;

    int niter = K / BK;
    LDG_TILE(0);
    STS_TILE(0);
    __syncthreads();

    for (int it = 0; it < niter; it++) {
        int cur = it & 1;
        bool more = (it + 1 < niter);
        if (more) LDG_TILE((it + 1) * BK);

        unsigned ah[2][4], al[2][4], bh[4][2], bl[4][2];
        #pragma unroll
        for (int mf = 0; mf < 2; mf++) {
            int rm = wm*32 + mf*16 + gid;
            ah[mf][0] = Ah[cur][rm    ][tig    ];
            ah[mf][1] = Ah[cur][rm + 8][tig    ];
            ah[mf][2] = Ah[cur][rm    ][tig + 4];
            ah[mf][3] = Ah[cur][rm + 8][tig + 4];
            al[mf][0] = Al[cur][rm    ][tig    ];
            al[mf][1] = Al[cur][rm + 8][tig    ];
            al[mf][2] = Al[cur][rm    ][tig + 4];
            al[mf][3] = Al[cur][rm + 8][tig + 4];
        }
        #pragma unroll
        for (int nf = 0; nf < 4; nf++) {
            int cn = wn*32 + nf*8 + gid;
            bh[nf][0] = Bh[cur][tig    ][cn];
            bh[nf][1] = Bh[cur][tig + 4][cn];
            bl[nf][0] = Bl[cur][tig    ][cn];
            bl[nf][1] = Bl[cur][tig + 4][cn];
        }
        #pragma unroll
        for (int mf = 0; mf < 2; mf++)
            #pragma unroll
            for (int nf = 0; nf < 4; nf++) {
                float* c = acc[mf][nf];
                MMA_BF16(c, ah[mf], bl[nf]);
                MMA_BF16(c, al[mf], bh[nf]);
                MMA_BF16(c, ah[mf], bh[nf]);
            }
        if (more) {
            STS_TILE(cur ^ 1);
            __syncthreads();
        }
    }

    // ---- epilogue ----
    bool do_stats = (ssum != nullptr);
    if (do_stats) {
        if (tid < BN) { s1[tid] = 0.f; s2[tid] = 0.f; }
        __syncthreads();
    }
    float lsum[4][2] = {}, lsq[4][2] = {};
    #pragma unroll
    for (int mf = 0; mf < 2; mf++) {
        #pragma unroll
        for (int nf = 0; nf < 4; nf++) {
            int r0 = bm + wm*32 + mf*16 + gid;
            int c0 = bn + wn*32 + nf*8 + 2*tig;
            float* c = acc[mf][nf];
            #pragma unroll
            for (int half = 0; half < 2; half++) {
                int r = r0 + half*8;
                float v0 = c[half*2+0], v1 = c[half*2+1];
                if (mode != 2) {
                    v0 += bias[c0]; v1 += bias[c0+1];
                    if (do_stats) {
                        lsum[nf][0] += v0;    lsum[nf][1] += v1;
                        lsq [nf][0] += v0*v0; lsq [nf][1] += v1*v1;
                    }
                    if (mode == 1) { v0 = fmaxf(v0, 0.f); v1 = fmaxf(v1, 0.f); }
                    *reinterpret_cast<float2*>(C + (size_t)r*N + c0) = make_float2(v0, v1);
                } else {
                    *reinterpret_cast<float2*>(C + (size_t)r*N + c0) = make_float2(v0, v1);
                    float2* y = reinterpret_cast<float2*>(Y + (size_t)r*N + c0);
                    float2 yo = *y;
                    yo.x += 0.25f*v0; yo.y += 0.25f*v1;
                    *y = yo;
                }
            }
        }
    }
    if (do_stats) {
        #pragma unroll
        for (int nf = 0; nf < 4; nf++) {
            int cl = wn*32 + nf*8 + 2*tig;
            atomicAdd(&s1[cl],   lsum[nf][0]);
            atomicAdd(&s1[cl+1], lsum[nf][1]);
            atomicAdd(&s2[cl],   lsq[nf][0]);
            atomicAdd(&s2[cl+1], lsq[nf][1]);
        }
        __syncthreads();
        if (tid < BN) {
            atomicAdd(&ssum[bn + tid], s1[tid]);
            atomicAdd(&ssq [bn + tid], s2[tid]);
        }
    }
#undef LDG_TILE
#undef STS_TILE
}

// ------------------------------ fused GIN kernels ---------------------------
// Computes hv = T(src) + vn (T = optional bn2+relu of previous layer),
// writes g_hin, aggregates relu(hv_src + eemb) over incoming edges into g_z.
__global__ void k_agg(const float* __restrict__ src,
                      const float* __restrict__ sc, const float* __restrict__ sh,
                      const float* __restrict__ eembL, const float* __restrict__ epsp,
                      const float* __restrict__ vnp, int vnstride) {
    int n = blockIdx.x, c = threadIdx.x;
    int b = n >> 8;
    float vnv = vnp[b*vnstride + c];
    float scv = 1.f, shv = 0.f;
    if (sc) { scv = sc[c]; shv = sh[c]; }
    int start = g_ptr[n], deg = g_deg[n];
    float own = src[(size_t)n*EMB + c];
    if (sc) own = fmaxf(own*scv + shv, 0.f);
    float hvn = own + vnv;
    g_hin[(size_t)n*EMB + c] = hvn;
    float val = 0.f;
    for (int k = 0; k < deg; k++) {
        int s = g_csrc[start + k];
        int t = g_cea [start + k];
        float x = src[(size_t)s*EMB + c];
        if (sc) x = fmaxf(x*scv + shv, 0.f);
        float m = x + vnv + eembL[t*EMB + c];
        val += fmaxf(m, 0.f);
    }
    g_z[(size_t)n*EMB + c] = (1.f + *epsp)*hvn + val;
}

// ------------------------------ batchnorm helpers ---------------------------
__global__ void k_zstat() {
    int i = blockIdx.x * 256 + threadIdx.x;
    if (i < 2*EMB) { g_sum[i] = 0.f; g_sq[i] = 0.f; }
}

__global__ void k_bnfin(const float* __restrict__ g, const float* __restrict__ b,
                        float* __restrict__ osc, float* __restrict__ osh, int C) {
    int c = blockIdx.x * 256 + threadIdx.x;
    if (c >= C) return;
    float mu  = g_sum[c] * (1.f / NTOT);
    float var = g_sq[c] * (1.f / NTOT) - mu * mu;
    float s   = g[c] * rsqrtf(var + 1e-5f);
    osc[c] = s;
    osh[c] = b[c] - mu * s;
}

// final-layer BN apply (no relu) straight to output
__global__ void k_bnout(const float* __restrict__ X, float* __restrict__ O) {
    int idx = blockIdx.x * 256 + threadIdx.x;
    int c = idx & 255;
    O[idx] = X[idx] * g_sc2[c] + g_sh2[c];
}

// vt[b] = sum_nodes hin + vn[b]
__global__ void k_vt(const float* __restrict__ vnp, int vnstride) {
    int b = blockIdx.x, c = threadIdx.x;
    const float* base = g_hin + (size_t)b*NPG*EMB + c;
    float s = 0.f;
    for (int r = 0; r < NPG; r++) s += base[(size_t)r*EMB];
    g_vt[b*EMB + c] = s + vnp[b*vnstride + c];
}

// ------------------------------ host orchestration --------------------------
extern "C" void kernel_launch(void* const* d_in, const int* in_sizes, int n_in,
                              void* d_out, int out_size) {
    const int ab = n_in - 19;
    const int*   atom_idx = (const int*)  d_in[0];
    const int*   lei      = (const int*)  d_in[1];
    const int*   eai      = (const int*)  d_in[2];
    const float* atom_emb = (const float*)d_in[ab + 0];
    const float* bemb_h   = (const float*)d_in[ab + 1];
    const float* elin_w   = (const float*)d_in[ab + 2];
    const float* elin_b   = (const float*)d_in[ab + 3];
    const float* bemb_l   = (const float*)d_in[ab + 4];
    const float* gin_eps  = (const float*)d_in[ab + 5];
    const float* mlp_w1   = (const float*)d_in[ab + 6];
    const float* mlp_b1   = (const float*)d_in[ab + 7];
    const float* bn_g     = (const float*)d_in[ab + 8];
    const float* bn_b     = (const float*)d_in[ab + 9];
    const float* mlp_w2   = (const float*)d_in[ab + 10];
    const float* mlp_b2   = (const float*)d_in[ab + 11];
    const float* obn_g    = (const float*)d_in[ab + 12];
    const float* obn_b    = (const float*)d_in[ab + 13];
    const float* vn_emb   = (const float*)d_in[ab + 14];
    const float* vn_w1    = (const float*)d_in[ab + 15];
    const float* vn_b1    = (const float*)d_in[ab + 16];
    const float* vn_w2    = (const float*)d_in[ab + 17];
    const float* vn_b2    = (const float*)d_in[ab + 18];
    float* out = (float*)d_out;

    float *p_x1, *p_x2, *p_z, *p_t, *p_h2, *p_h, *p_vt, *p_vh, *p_vn, *p_A;
    float *p_sum, *p_sq, *p_sc1, *p_sh1, *p_sc2, *p_sh2;
    cudaGetSymbolAddress((void**)&p_x1, g_x1);
    cudaGetSymbolAddress((void**)&p_x2, g_x2);
    cudaGetSymbolAddress((void**)&p_z,  g_z);
    cudaGetSymbolAddress((void**)&p_t,  g_t);
    cudaGetSymbolAddress((void**)&p_h2, g_h2);
    cudaGetSymbolAddress((void**)&p_h,  g_h);
    cudaGetSymbolAddress((void**)&p_vt, g_vt);
    cudaGetSymbolAddress((void**)&p_vh, g_vh);
    cudaGetSymbolAddress((void**)&p_vn, g_vn);
    cudaGetSymbolAddress((void**)&p_A,  g_A);
    cudaGetSymbolAddress((void**)&p_sum, g_sum);
    cudaGetSymbolAddress((void**)&p_sq,  g_sq);
    cudaGetSymbolAddress((void**)&p_sc1, g_sc1);
    cudaGetSymbolAddress((void**)&p_sh1, g_sh1);
    cudaGetSymbolAddress((void**)&p_sc2, g_sc2);
    cudaGetSymbolAddress((void**)&p_sh2, g_sh2);

    const int NE = NTOT*EMB/256;

    // ---- setup ----
    k_zero<<<(int)(((size_t)BG*NPG*NPG + 255)/256), 256>>>();
    k_ewt<<<1, 512>>>(bemb_h, elin_w, elin_b);
    k_scatter<<<ETOT/256, 256>>>(lei, eai);
    k_adjfin<<<BG, 256>>>();
    k_scan<<<BG, 256>>>();
    k_csrfill<<<ETOT/256, 256>>>(lei, eai);
    k_gather<<<NE, 256>>>(atom_idx, atom_emb);

    // ---- propagation: h = 0.25*(f + Af + A^2 f + A^3 f) ----
    dim3 pgrid(NPG/BN, NPG/BM, BG);
    long sA = (long)NPG*NPG, sX = (long)NPG*EMB;
    k_mma<<<pgrid, 256>>>(p_A, p_x1, nullptr, p_x2, p_h, NPG, EMB, NPG, 2, sA, sX, sX,
                          nullptr, nullptr, nullptr, nullptr);
    k_mma<<<pgrid, 256>>>(p_A, p_x2, nullptr, p_x1, p_h, NPG, EMB, NPG, 2, sA, sX, sX,
                          nullptr, nullptr, nullptr, nullptr);
    k_mma<<<pgrid, 256>>>(p_A, p_x1, nullptr, p_x2, p_h, NPG, EMB, NPG, 2, sA, sX, sX,
                          nullptr, nullptr, nullptr, nullptr);

    // ---- GIN + virtual-node stack ----
    const float* src = p_h;           // layer-0 node features
    const float* sc2 = nullptr;       // bn2 params of previous layer
    const float* sh2 = nullptr;
    const float* vnp = vn_emb;        // layer-0 vn (broadcast)
    int vnstride = 0;

    for (int l = 0; l < NL; l++) {
        // fused: (bn2+relu of prev layer) + vn add + hin store + GIN aggregate
        k_agg<<<NTOT, 256>>>(src, sc2, sh2,
                             bemb_l + (size_t)l*16*EMB, gin_eps + l, vnp, vnstride);

        // GEMM1: t = z @ w1 + b1  (stats fused)
        k_zstat<<<2, 256>>>();
        k_mma<<<dim3(2*EMB/BN, NTOT/BM, 1), 256>>>(
            p_z, mlp_w1 + (size_t)l*EMB*2*EMB, mlp_b1 + (size_t)l*2*EMB,
            p_t, nullptr, NTOT, 2*EMB, EMB, 0, 0, 0, 0,
            nullptr, nullptr, p_sum, p_sq);
        k_bnfin<<<2, 256>>>(bn_g + (size_t)l*2*EMB, bn_b + (size_t)l*2*EMB,
                            p_sc1, p_sh1, 2*EMB);

        // GEMM2: h2 = relu(bn1(t)) @ w2 + b2   (bn1+relu fused in A-load, stats fused)
        k_zstat<<<2, 256>>>();
        k_mma<<<dim3(EMB/BN, NTOT/BM, 1), 256>>>(
            p_t, mlp_w2 + (size_t)l*2*EMB*EMB, mlp_b2 + (size_t)l*EMB,
            p_h2, nullptr, NTOT, EMB, 2*EMB, 0, 0, 0, 0,
            p_sc1, p_sh1, p_sum, p_sq);
        k_bnfin<<<1, 256>>>(obn_g + (size_t)l*EMB, obn_b + (size_t)l*EMB,
                            p_sc2, p_sh2, EMB);

        if (l < NL - 1) {
            k_vt<<<BG, 256>>>(vnp, vnstride);
            k_mma<<<dim3(2*EMB/BN, BG/BM, 1), 256>>>(
                p_vt, vn_w1 + (size_t)l*EMB*2*EMB, vn_b1 + (size_t)l*2*EMB,
                p_vh, nullptr, BG, 2*EMB, EMB, 1, 0, 0, 0,
                nullptr, nullptr, nullptr, nullptr);
            k_mma<<<dim3(EMB/BN, BG/BM, 1), 256>>>(
                p_vh, vn_w2 + (size_t)l*2*EMB*EMB, vn_b2 + (size_t)l*EMB,
                p_vn, nullptr, BG, EMB, 2*EMB, 1, 0, 0, 0,
                nullptr, nullptr, nullptr, nullptr);
        }

        src = p_h2;
        sc2 = p_sc2; sh2 = p_sh2;
        vnp = p_vn; vnstride = EMB;
    }

    // final: out = bn2(h2), no relu
    k_bnout<<<NE, 256>>>(p_h2, out);
    (void)in_sizes; (void)out_size;
}